// round 7
// baseline (speedup 1.0000x reference)
#include <cuda_runtime.h>
#include <cuda_fp16.h>
#include <cstdint>

#define NS    51
#define ROWS  64
#define TSEQ  2048
#define BATCH 8192
#define NCTA  (BATCH / ROWS)
#define NTH   256
#define KC1   4
#define KC2   7
#define ST1   72
#define ST2   120
#define CHUNK 16
#define XSTR  17

#define OFF_A1   0
#define OFF_A2   9216
#define OFF_B1F  24576
#define OFF_B2F  51200            // v4-paired part: 26*3*512 = 39936
#define OFF_B2T  91136            // kc6 tail: 26*256 = 6656
#define OFF_XS   97792
#define OFF_YS   102144
#define OFF_YP   106496
#define OFF_WL   107520
#define SMEM_BYTES 107904

__device__ __forceinline__ uint32_t smem_u32(const void* p) {
    uint32_t a;
    asm("{ .reg .u64 t; cvta.to.shared.u64 t, %1; cvt.u32.u64 %0, t; }" : "=r"(a) : "l"(p));
    return a;
}
__device__ __forceinline__ void sts16h(uint32_t a, float v) {
    unsigned short h = __half_as_ushort(__float2half_rn(v));
    asm volatile("st.shared.b16 [%0], %1;" :: "r"(a), "h"(h) : "memory");
}
__device__ __forceinline__ void sts32(uint32_t a, float v) {
    asm volatile("st.shared.b32 [%0], %1;" :: "r"(a), "f"(v) : "memory");
}
__device__ __forceinline__ void sts32u(uint32_t a, uint32_t v) {
    asm volatile("st.shared.b32 [%0], %1;" :: "r"(a), "r"(v) : "memory");
}
__device__ __forceinline__ float lds32(uint32_t a) {
    float v;
    asm volatile("ld.shared.b32 %0, [%1];" : "=f"(v) : "r"(a));
    return v;
}
__device__ __forceinline__ void lds64u(uint32_t& v0, uint32_t& v1, uint32_t a) {
    asm volatile("ld.shared.v2.b32 {%0,%1}, [%2];" : "=r"(v0), "=r"(v1) : "r"(a));
}
__device__ __forceinline__ void lds128u(uint32_t& v0, uint32_t& v1, uint32_t& v2,
                                        uint32_t& v3, uint32_t a) {
    asm volatile("ld.shared.v4.b32 {%0,%1,%2,%3}, [%4];"
                 : "=r"(v0), "=r"(v1), "=r"(v2), "=r"(v3) : "r"(a));
}
__device__ __forceinline__ void ldsm4(uint32_t* r, uint32_t a) {
    asm volatile("ldmatrix.sync.aligned.m8n8.x4.shared.b16 {%0,%1,%2,%3}, [%4];"
                 : "=r"(r[0]), "=r"(r[1]), "=r"(r[2]), "=r"(r[3]) : "r"(a));
}
__device__ __forceinline__ void hmma(float* d, const uint32_t* a, uint32_t b0, uint32_t b1) {
    asm volatile(
        "mma.sync.aligned.m16n8k16.row.col.f32.f16.f16.f32 "
        "{%0,%1,%2,%3}, {%4,%5,%6,%7}, {%8,%9}, {%0,%1,%2,%3};"
        : "+f"(d[0]), "+f"(d[1]), "+f"(d[2]), "+f"(d[3])
        : "r"(a[0]), "r"(a[1]), "r"(a[2]), "r"(a[3]), "r"(b0), "r"(b1));
}
__device__ __forceinline__ float ex2_(float x) {
    float r;
    asm("ex2.approx.ftz.f32 %0, %1;" : "=f"(r) : "f"(x));
    return r;
}
__device__ __forceinline__ float rcp_(float x) {
    float r;
    asm("rcp.approx.ftz.f32 %0, %1;" : "=f"(r) : "f"(x));
    return r;
}
// Merged LSTM cell: 5 ex2 + 2 rcp.
__device__ __forceinline__ float cell(float gi, float gf, float gg, float go, float& c) {
    const float L2E = 1.4426950408889634f;
    float a = ex2_(-L2E * gi);
    float b = ex2_(-2.f * L2E * gg);
    float u = ex2_(-L2E * gf);
    float pa = 1.f + a, pb = 1.f + b, pu = 1.f + u;
    float papb = pa * pb;
    float num = fmaf(1.f - b, pu, c * papb);
    c = num * rcp_(papb * pu);
    float o = ex2_(-L2E * go);
    float d2 = ex2_(-2.f * L2E * c);
    return (1.f - d2) * rcp_((1.f + o) * (1.f + d2));
}

__device__ float w1val(int n, int k, const float* Whh1, const float* Wih1,
                       const float* bih1, const float* bhh1) {
    int u = n >> 2, g = n & 3;
    if (u >= NS) return 0.f;
    int gu = g * NS + u;
    if (k < NS) return Whh1[gu * NS + k];
    if (k == 52) return Wih1[gu];
    if (k == 53) return bih1[gu] + bhh1[gu];
    return 0.f;
}
__device__ float w2val(int n, int k, const float* Wih2, const float* Whh2,
                       const float* bih2, const float* bhh2) {
    int u = n >> 2, g = n & 3;
    if (u >= NS) return 0.f;
    int gu = g * NS + u;
    if (k < NS) return Wih2[gu * NS + k];
    if (k >= 52 && k - 52 < NS) return Whh2[gu * NS + (k - 52)];
    if (k == 104) return bih2[gu] + bhh2[gu];
    return 0.f;
}

extern __shared__ char smraw[];

__global__ __launch_bounds__(NTH, 1)
void lstm2_hmma_kernel(const float* __restrict__ x,
                       const float* __restrict__ Wih1, const float* __restrict__ Whh1,
                       const float* __restrict__ bih1, const float* __restrict__ bhh1,
                       const float* __restrict__ Wih2, const float* __restrict__ Whh2,
                       const float* __restrict__ bih2, const float* __restrict__ bhh2,
                       const float* __restrict__ Wlin, const float* __restrict__ blin,
                       float* __restrict__ out) {
    const uint32_t s0 = smem_u32(smraw);
    const int tid = threadIdx.x;
    const int wid = tid >> 5;
    const int lane = tid & 31;

    // ---- one-time pack ----
    for (int i = tid; i < OFF_B1F / 4; i += NTH) sts32(s0 + i * 4, 0.f);
    // B1: [nt][p][lane][w], word = half2 of gate col n, k..k+1; kc = 2p + (w>>1)
    for (int idx = tid; idx < 26 * 2 * 32 * 4; idx += NTH) {
        int w = idx & 3, ln = (idx >> 2) & 31, p = (idx >> 7) & 1, nt = idx >> 8;
        int n = nt * 8 + (ln >> 2);
        int kcc = 2 * p + (w >> 1);
        int k = kcc * 16 + (ln & 3) * 2 + (w & 1) * 8;
        __half2 hv = __floats2half2_rn(w1val(n, k, Whh1, Wih1, bih1, bhh1),
                                       w1val(n, k + 1, Whh1, Wih1, bih1, bhh1));
        sts32u(s0 + OFF_B1F + idx * 4, *reinterpret_cast<uint32_t*>(&hv));
    }
    // B2 v4-part: [nt][p=0..2][lane][w]; kc = 2p + (w>>1)  (kc 0..5)
    for (int idx = tid; idx < 26 * 3 * 32 * 4; idx += NTH) {
        int nt = idx / 384, r = idx - nt * 384;
        int p = r >> 7, ln = (r >> 2) & 31, w = r & 3;
        int n = nt * 8 + (ln >> 2);
        int kcc = 2 * p + (w >> 1);
        int k = kcc * 16 + (ln & 3) * 2 + (w & 1) * 8;
        __half2 hv = __floats2half2_rn(w2val(n, k, Wih2, Whh2, bih2, bhh2),
                                       w2val(n, k + 1, Wih2, Whh2, bih2, bhh2));
        sts32u(s0 + OFF_B2F + idx * 4, *reinterpret_cast<uint32_t*>(&hv));
    }
    // B2 tail: kc=6, [nt][lane][w]
    for (int idx = tid; idx < 26 * 32 * 2; idx += NTH) {
        int w = idx & 1, ln = (idx >> 1) & 31, nt = idx >> 6;
        int n = nt * 8 + (ln >> 2);
        int k = 6 * 16 + (ln & 3) * 2 + w * 8;
        __half2 hv = __floats2half2_rn(w2val(n, k, Wih2, Whh2, bih2, bhh2),
                                       w2val(n, k + 1, Wih2, Whh2, bih2, bhh2));
        sts32u(s0 + OFF_B2T + idx * 4, *reinterpret_cast<uint32_t*>(&hv));
    }
    if (tid < ROWS) {
        sts16h(s0 + OFF_A1 + (tid * ST1 + 53) * 2, 1.f);
        sts16h(s0 + OFF_A2 + (tid * ST2 + 104) * 2, 1.f);
    }
    for (int u = tid; u < 52; u += NTH)
        sts32(s0 + OFF_WL + u * 4, (u < NS) ? Wlin[u] : 0.f);
    __syncthreads();

    // ---- mapping: pair = wid>>1 so each SMSP hosts 2 DIFFERENT pairs ----
    const int mt = wid >> 1;          // pair / m-tile
    const int nh = wid & 1;           // n-half within pair
    const int ptid = nh * 32 + lane;
    const int barid = mt + 1;
    const bool odd = lane & 1;
    const int rowE = mt * 16 + (lane >> 2) + (odd ? 8 : 0);
    const int ubase = 26 * nh + ((lane >> 1) & 1);
    const long long rb = (long long)blockIdx.x * ROWS;
    const float bl = blin[0];

    const int lrow = mt * 16 + (lane & 15);
    const uint32_t khalf = ((lane >> 4) & 1) * 16;
    const uint32_t a1m = s0 + OFF_A1 + lrow * ST1 * 2 + khalf;
    const uint32_t a2m = s0 + OFF_A2 + lrow * ST2 * 2 + khalf;
    const uint32_t b1p = s0 + OFF_B1F + nh * 13 * 1024 + lane * 16;
    const uint32_t b2p = s0 + OFF_B2F + nh * 13 * 1536 + lane * 16;
    const uint32_t b2t = s0 + OFF_B2T + nh * 13 * 256 + lane * 8;
    const uint32_t hwA1 = s0 + OFF_A1 + rowE * ST1 * 2 + ubase * 2;
    const uint32_t hwA2 = s0 + OFF_A2 + rowE * ST2 * 2 + ubase * 2;
    const uint32_t hwA2b = hwA2 + 104;

    float wl[13];
#pragma unroll
    for (int j = 0; j < 13; j++) wl[j] = lds32(s0 + OFF_WL + (ubase + 2 * j) * 4);

    float c1[13], c2[13], h1v[13], h2v[13];
#pragma unroll
    for (int i = 0; i < 13; i++) { c1[i] = 0.f; c2[i] = 0.f; h1v[i] = 0.f; h2v[i] = 0.f; }

#define PBAR() asm volatile("bar.sync %0, 64;" :: "r"(barid) : "memory")

    for (int t = 0; t < TSEQ; t++) {
        const int tc = t & (CHUNK - 1);

        if (t) {
#pragma unroll
            for (int j = 0; j < 13; j++) sts16h(hwA2b + 4 * j, h2v[j]);
            if (ptid < 16) {
                int row = mt * 16 + ptid;
                uint32_t ypb = s0 + OFF_YP + row * 16;
                float y = lds32(ypb) + lds32(ypb + 4) + lds32(ypb + 8) + lds32(ypb + 12) + bl;
                sts32(s0 + OFF_YS + (row * XSTR + ((t - 1) & (CHUNK - 1))) * 4, y);
            }
        }
        if (tc == 0) {
            PBAR();
            if (t) {
                const int t0 = t - CHUNK;
                for (int idx = ptid; idx < 256; idx += 64) {
                    int rl = idx >> 4, cc = idx & 15, row = mt * 16 + rl;
                    out[(rb + row) * TSEQ + t0 + cc] = lds32(s0 + OFF_YS + (row * XSTR + cc) * 4);
                }
            }
            for (int idx = ptid; idx < 256; idx += 64) {
                int rl = idx >> 4, cc = idx & 15, row = mt * 16 + rl;
                float xv = x[(rb + row) * TSEQ + t + cc];
                sts32(s0 + OFF_XS + (row * XSTR + cc) * 4, xv);
                if (cc == 0) sts16h(s0 + OFF_A1 + (row * ST1 + 52) * 2, xv);
            }
            PBAR();
        }

        // ---- gemm1 ----
        uint32_t af[KC2][4];
        float d[13][4];
#pragma unroll
        for (int kc = 0; kc < KC1; kc++) ldsm4(af[kc], a1m + kc * 32);
#pragma unroll
        for (int j = 0; j < 13; j++) {
            d[j][0] = d[j][1] = d[j][2] = d[j][3] = 0.f;
            uint32_t b0, b1, b2, b3;
            lds128u(b0, b1, b2, b3, b1p + j * 1024);
            hmma(d[j], af[0], b0, b1);
            hmma(d[j], af[1], b2, b3);
            lds128u(b0, b1, b2, b3, b1p + j * 1024 + 512);
            hmma(d[j], af[2], b0, b1);
            hmma(d[j], af[3], b2, b3);
        }
        // ---- epilogue 1 ----
#pragma unroll
        for (int j = 0; j < 13; j++) {
            float t0s = odd ? d[j][0] : d[j][2];
            float t1s = odd ? d[j][1] : d[j][3];
            float rx0 = __shfl_xor_sync(0xffffffffu, t0s, 1);
            float rx1 = __shfl_xor_sync(0xffffffffu, t1s, 1);
            float gi = odd ? rx0 : d[j][0];
            float gf = odd ? rx1 : d[j][1];
            float gg = odd ? d[j][2] : rx0;
            float go = odd ? d[j][3] : rx1;
            float h = cell(gi, gf, gg, go, c1[j]);
            h1v[j] = h;
            sts16h(hwA2 + 4 * j, h);
        }
        PBAR();   // BAR_mid

#pragma unroll
        for (int j = 0; j < 13; j++) sts16h(hwA1 + 4 * j, h1v[j]);

        // ---- gemm2 ----
#pragma unroll
        for (int kc = 0; kc < KC2; kc++) ldsm4(af[kc], a2m + kc * 32);
#pragma unroll
        for (int j = 0; j < 13; j++) {
            d[j][0] = d[j][1] = d[j][2] = d[j][3] = 0.f;
            uint32_t b0, b1, b2, b3;
            lds128u(b0, b1, b2, b3, b2p + j * 1536);
            hmma(d[j], af[0], b0, b1);
            hmma(d[j], af[1], b2, b3);
            lds128u(b0, b1, b2, b3, b2p + j * 1536 + 512);
            hmma(d[j], af[2], b0, b1);
            hmma(d[j], af[3], b2, b3);
            lds128u(b0, b1, b2, b3, b2p + j * 1536 + 1024);
            hmma(d[j], af[4], b0, b1);
            hmma(d[j], af[5], b2, b3);
            lds64u(b0, b1, b2t + j * 256);
            hmma(d[j], af[6], b0, b1);
        }
        // ---- epilogue 2 ----
        float yp = 0.f;
#pragma unroll
        for (int j = 0; j < 13; j++) {
            float t0s = odd ? d[j][0] : d[j][2];
            float t1s = odd ? d[j][1] : d[j][3];
            float rx0 = __shfl_xor_sync(0xffffffffu, t0s, 1);
            float rx1 = __shfl_xor_sync(0xffffffffu, t1s, 1);
            float gi = odd ? rx0 : d[j][0];
            float gf = odd ? rx1 : d[j][1];
            float gg = odd ? d[j][2] : rx0;
            float go = odd ? d[j][3] : rx1;
            float h = cell(gi, gf, gg, go, c2[j]);
            h2v[j] = h;
            yp = fmaf(h, wl[j], yp);
        }
        sts32(s0 + OFF_YP + (rowE * 4 + nh * 2 + ((lane >> 1) & 1)) * 4, yp);
        if (tc < CHUNK - 1 && ptid < 16) {
            int row = mt * 16 + ptid;
            sts16h(s0 + OFF_A1 + (row * ST1 + 52) * 2,
                   lds32(s0 + OFF_XS + (row * XSTR + tc + 1) * 4));
        }
        PBAR();   // BAR_end
    }

    if (ptid < 16) {
        int row = mt * 16 + ptid;
        uint32_t ypb = s0 + OFF_YP + row * 16;
        float y = lds32(ypb) + lds32(ypb + 4) + lds32(ypb + 8) + lds32(ypb + 12) + bl;
        sts32(s0 + OFF_YS + (row * XSTR + (CHUNK - 1)) * 4, y);
    }
    PBAR();
    for (int idx = ptid; idx < 256; idx += 64) {
        int rl = idx >> 4, cc = idx & 15, row = mt * 16 + rl;
        out[(rb + row) * TSEQ + (TSEQ - CHUNK) + cc] = lds32(s0 + OFF_YS + (row * XSTR + cc) * 4);
    }
#undef PBAR
}

extern "C" void kernel_launch(void* const* d_in, const int* in_sizes, int n_in,
                              void* d_out, int out_size) {
    const float* x    = (const float*)d_in[0];
    const float* Wih1 = (const float*)d_in[1];
    const float* Whh1 = (const float*)d_in[2];
    const float* bih1 = (const float*)d_in[3];
    const float* bhh1 = (const float*)d_in[4];
    const float* Wih2 = (const float*)d_in[5];
    const float* Whh2 = (const float*)d_in[6];
    const float* bih2 = (const float*)d_in[7];
    const float* bhh2 = (const float*)d_in[8];
    const float* Wlin = (const float*)d_in[9];
    const float* blin = (const float*)d_in[10];

    cudaFuncSetAttribute(lstm2_hmma_kernel,
                         cudaFuncAttributeMaxDynamicSharedMemorySize, SMEM_BYTES);
    lstm2_hmma_kernel<<<NCTA, NTH, SMEM_BYTES>>>(
        x, Wih1, Whh1, bih1, bhh1, Wih2, Whh2, bih2, bhh2, Wlin, blin,
        (float*)d_out);
}

// round 8
// speedup vs baseline: 1.0576x; 1.0576x over previous
#include <cuda_runtime.h>
#include <cuda_fp16.h>
#include <cstdint>

#define NS    51
#define ROWS  64
#define TSEQ  2048
#define BATCH 8192
#define NCTA  (BATCH / ROWS)
#define NTH   256
#define KC1   4
#define KC2   7
#define ST1   72
#define ST2   120
#define CHUNK 16
#define XSTR  17

#define A1SZ  9216            // one A1 buffer (64*72*2)
#define A2SZ  15360           // one A2 buffer (64*120*2)
#define OFF_A1   0            // 2 buffers -> 18432
#define OFF_A2   18432        // 2 buffers -> 30720, end 49152
#define OFF_B1F  49152        // 26624 -> 75776
#define OFF_B2F  75776        // 46592 -> 122368
#define OFF_XS   122368       // 4352  -> 126720
#define OFF_YP   126720       // 16 slots * 64 rows * 4 parts * 4B = 16384 -> 143104
#define OFF_WL   143104       // 208
#define SMEM_BYTES 143360

__device__ __forceinline__ uint32_t smem_u32(const void* p) {
    uint32_t a;
    asm("{ .reg .u64 t; cvta.to.shared.u64 t, %1; cvt.u32.u64 %0, t; }" : "=r"(a) : "l"(p));
    return a;
}
__device__ __forceinline__ void sts16h(uint32_t a, float v) {
    unsigned short h = __half_as_ushort(__float2half_rn(v));
    asm volatile("st.shared.b16 [%0], %1;" :: "r"(a), "h"(h) : "memory");
}
__device__ __forceinline__ void sts32(uint32_t a, float v) {
    asm volatile("st.shared.b32 [%0], %1;" :: "r"(a), "f"(v) : "memory");
}
__device__ __forceinline__ void sts32u(uint32_t a, uint32_t v) {
    asm volatile("st.shared.b32 [%0], %1;" :: "r"(a), "r"(v) : "memory");
}
__device__ __forceinline__ float lds32(uint32_t a) {
    float v;
    asm volatile("ld.shared.b32 %0, [%1];" : "=f"(v) : "r"(a));
    return v;
}
__device__ __forceinline__ void lds64u(uint32_t& v0, uint32_t& v1, uint32_t a) {
    asm volatile("ld.shared.v2.b32 {%0,%1}, [%2];" : "=r"(v0), "=r"(v1) : "r"(a));
}
__device__ __forceinline__ void ldsm4(uint32_t* r, uint32_t a) {
    asm volatile("ldmatrix.sync.aligned.m8n8.x4.shared.b16 {%0,%1,%2,%3}, [%4];"
                 : "=r"(r[0]), "=r"(r[1]), "=r"(r[2]), "=r"(r[3]) : "r"(a));
}
__device__ __forceinline__ void hmma(float* d, const uint32_t* a, uint32_t b0, uint32_t b1) {
    asm volatile(
        "mma.sync.aligned.m16n8k16.row.col.f32.f16.f16.f32 "
        "{%0,%1,%2,%3}, {%4,%5,%6,%7}, {%8,%9}, {%0,%1,%2,%3};"
        : "+f"(d[0]), "+f"(d[1]), "+f"(d[2]), "+f"(d[3])
        : "r"(a[0]), "r"(a[1]), "r"(a[2]), "r"(a[3]), "r"(b0), "r"(b1));
}
__device__ __forceinline__ float ex2_(float x) {
    float r;
    asm("ex2.approx.ftz.f32 %0, %1;" : "=f"(r) : "f"(x));
    return r;
}
__device__ __forceinline__ float rcp_(float x) {
    float r;
    asm("rcp.approx.ftz.f32 %0, %1;" : "=f"(r) : "f"(x));
    return r;
}
// Merged LSTM cell: 5 ex2 + 2 rcp.
__device__ __forceinline__ float cell(float gi, float gf, float gg, float go, float& c) {
    const float L2E = 1.4426950408889634f;
    float a = ex2_(-L2E * gi);
    float b = ex2_(-2.f * L2E * gg);
    float u = ex2_(-L2E * gf);
    float pa = 1.f + a, pb = 1.f + b, pu = 1.f + u;
    float papb = pa * pb;
    float num = fmaf(1.f - b, pu, c * papb);
    c = num * rcp_(papb * pu);
    float o = ex2_(-L2E * go);
    float d2 = ex2_(-2.f * L2E * c);
    return (1.f - d2) * rcp_((1.f + o) * (1.f + d2));
}

__device__ float w1val(int n, int k, const float* Whh1, const float* Wih1,
                       const float* bih1, const float* bhh1) {
    int u = n >> 2, g = n & 3;
    if (u >= NS) return 0.f;
    int gu = g * NS + u;
    if (k < NS) return Whh1[gu * NS + k];
    if (k == 52) return Wih1[gu];
    if (k == 53) return bih1[gu] + bhh1[gu];
    return 0.f;
}
__device__ float w2val(int n, int k, const float* Wih2, const float* Whh2,
                       const float* bih2, const float* bhh2) {
    int u = n >> 2, g = n & 3;
    if (u >= NS) return 0.f;
    int gu = g * NS + u;
    if (k < NS) return Wih2[gu * NS + k];
    if (k >= 52 && k - 52 < NS) return Whh2[gu * NS + (k - 52)];
    if (k == 104) return bih2[gu] + bhh2[gu];
    return 0.f;
}

extern __shared__ char smraw[];

__global__ __launch_bounds__(NTH, 1)
void lstm2_hmma_kernel(const float* __restrict__ x,
                       const float* __restrict__ Wih1, const float* __restrict__ Whh1,
                       const float* __restrict__ bih1, const float* __restrict__ bhh1,
                       const float* __restrict__ Wih2, const float* __restrict__ Whh2,
                       const float* __restrict__ bih2, const float* __restrict__ bhh2,
                       const float* __restrict__ Wlin, const float* __restrict__ blin,
                       float* __restrict__ out) {
    const uint32_t s0 = smem_u32(smraw);
    const int tid = threadIdx.x;
    const int wid = tid >> 5;
    const int lane = tid & 31;

    // ---- one-time pack ----
    for (int i = tid; i < OFF_B1F / 4; i += NTH) sts32(s0 + i * 4, 0.f);   // zero both A1+A2 buffers
    // B1 fragments: [nt][kc][lane][w] (R6 layout, v2 loads)
    for (int idx = tid; idx < 26 * KC1 * 64; idx += NTH) {
        int w = idx & 1, ln = (idx >> 1) & 31, kc = (idx >> 6) & 3, nt = idx >> 8;
        int n = nt * 8 + (ln >> 2);
        int k = kc * 16 + (ln & 3) * 2 + w * 8;
        __half2 hv = __floats2half2_rn(w1val(n, k, Whh1, Wih1, bih1, bhh1),
                                       w1val(n, k + 1, Whh1, Wih1, bih1, bhh1));
        sts32u(s0 + OFF_B1F + idx * 4, *reinterpret_cast<uint32_t*>(&hv));
    }
    // B2 fragments: [nt][kc][lane][w]
    for (int idx = tid; idx < 26 * KC2 * 64; idx += NTH) {
        int w = idx & 1, ln = (idx >> 1) & 31;
        int r = idx >> 6;
        int kc = r % KC2, nt = r / KC2;
        int n = nt * 8 + (ln >> 2);
        int k = kc * 16 + (ln & 3) * 2 + w * 8;
        __half2 hv = __floats2half2_rn(w2val(n, k, Wih2, Whh2, bih2, bhh2),
                                       w2val(n, k + 1, Wih2, Whh2, bih2, bhh2));
        sts32u(s0 + OFF_B2F + ((nt * KC2 + kc) * 64 + ln * 2 + w) * 4,
               *reinterpret_cast<uint32_t*>(&hv));
    }
    if (tid < ROWS) {   // const-1 columns in BOTH buffers
        sts16h(s0 + OFF_A1 + (tid * ST1 + 53) * 2, 1.f);
        sts16h(s0 + OFF_A1 + A1SZ + (tid * ST1 + 53) * 2, 1.f);
        sts16h(s0 + OFF_A2 + (tid * ST2 + 104) * 2, 1.f);
        sts16h(s0 + OFF_A2 + A2SZ + (tid * ST2 + 104) * 2, 1.f);
    }
    for (int u = tid; u < 52; u += NTH)
        sts32(s0 + OFF_WL + u * 4, (u < NS) ? Wlin[u] : 0.f);
    __syncthreads();

    // ---- mapping (R6: pair warps share an SMSP) ----
    const int mt = wid & 3;
    const int nh = wid >> 2;
    const int ptid = nh * 32 + lane;
    const int barid = mt + 1;
    const bool odd = lane & 1;
    const int rowE = mt * 16 + (lane >> 2) + (odd ? 8 : 0);
    const int ubase = 26 * nh + ((lane >> 1) & 1);
    const long long rb = (long long)blockIdx.x * ROWS;
    const float bl = blin[0];

    const int lrow = mt * 16 + (lane & 15);
    const uint32_t khalf = ((lane >> 4) & 1) * 16;
    const uint32_t a1m = s0 + OFF_A1 + lrow * ST1 * 2 + khalf;
    const uint32_t a2m = s0 + OFF_A2 + lrow * ST2 * 2 + khalf;
    const uint32_t b1p = s0 + OFF_B1F + (nh * 13 * KC1 * 64 + lane * 2) * 4;
    const uint32_t b2p = s0 + OFF_B2F + (nh * 13 * KC2 * 64 + lane * 2) * 4;
    const uint32_t hwA1 = s0 + OFF_A1 + rowE * ST1 * 2 + ubase * 2;
    const uint32_t hwA2 = s0 + OFF_A2 + rowE * ST2 * 2 + ubase * 2;
    const uint32_t ypw  = s0 + OFF_YP + (rowE * 4 + nh * 2 + ((lane >> 1) & 1)) * 4;

    float wl[13];
#pragma unroll
    for (int j = 0; j < 13; j++) wl[j] = lds32(s0 + OFF_WL + (ubase + 2 * j) * 4);

    float c1[13], c2[13];
#pragma unroll
    for (int i = 0; i < 13; i++) { c1[i] = 0.f; c2[i] = 0.f; }

#define PBAR() asm volatile("bar.sync %0, 64;" :: "r"(barid) : "memory")

    for (int t = 0; t < TSEQ; t++) {
        const int tc = t & (CHUNK - 1);
        const uint32_t bA1 = (uint32_t)(t & 1) * A1SZ, nA1 = A1SZ - bA1;
        const uint32_t bA2 = (uint32_t)(t & 1) * A2SZ, nA2 = A2SZ - bA2;

        if (tc == 0) {
            PBAR();
            if (t) {   // reduce + flush previous chunk straight from YP ring
                for (int idx = ptid; idx < 256; idx += 64) {
                    int rl = idx >> 4, cc = idx & 15, row = mt * 16 + rl;
                    uint32_t ypb = s0 + OFF_YP + (cc * 256 + row * 4) * 4;
                    float y = lds32(ypb) + lds32(ypb + 4) + lds32(ypb + 8) + lds32(ypb + 12) + bl;
                    out[(rb + row) * TSEQ + (t - CHUNK) + cc] = y;
                }
            }
            for (int idx = ptid; idx < 256; idx += 64) {
                int rl = idx >> 4, cc = idx & 15, row = mt * 16 + rl;
                float xv = x[(rb + row) * TSEQ + t + cc];
                sts32(s0 + OFF_XS + (row * XSTR + cc) * 4, xv);
                if (cc == 0) sts16h(s0 + OFF_A1 + bA1 + (row * ST1 + 52) * 2, xv);
            }
            PBAR();
        }

        // ---- gemm1(t): A1[b] ----
        uint32_t af[KC2][4];
        float d[13][4];
#pragma unroll
        for (int kc = 0; kc < KC1; kc++) ldsm4(af[kc], a1m + bA1 + kc * 32);
#pragma unroll
        for (int j = 0; j < 13; j++) {
            d[j][0] = d[j][1] = d[j][2] = d[j][3] = 0.f;
#pragma unroll
            for (int kc = 0; kc < KC1; kc++) {
                uint32_t b0, b1;
                lds64u(b0, b1, b1p + (j * KC1 + kc) * 256);
                hmma(d[j], af[kc], b0, b1);
            }
        }
        // ---- epilogue 1: h1 -> A2[b] (gemm2(t)) and A1[nb] (gemm1(t+1)) ----
#pragma unroll
        for (int j = 0; j < 13; j++) {
            float t0s = odd ? d[j][0] : d[j][2];
            float t1s = odd ? d[j][1] : d[j][3];
            float rx0 = __shfl_xor_sync(0xffffffffu, t0s, 1);
            float rx1 = __shfl_xor_sync(0xffffffffu, t1s, 1);
            float gi = odd ? rx0 : d[j][0];
            float gf = odd ? rx1 : d[j][1];
            float gg = odd ? d[j][2] : rx0;
            float go = odd ? d[j][3] : rx1;
            float h = cell(gi, gf, gg, go, c1[j]);
            sts16h(hwA2 + bA2 + 4 * j, h);
            sts16h(hwA1 + nA1 + 4 * j, h);
        }
        // x(t+1) -> A1[nb] col 52 (within chunk)
        if (tc < CHUNK - 1 && ptid < 16) {
            int row = mt * 16 + ptid;
            sts16h(s0 + OFF_A1 + nA1 + (row * ST1 + 52) * 2,
                   lds32(s0 + OFF_XS + (row * XSTR + tc + 1) * 4));
        }
        PBAR();   // the ONLY per-step barrier

        // ---- gemm2(t): A2[b] ----
#pragma unroll
        for (int kc = 0; kc < KC2; kc++) ldsm4(af[kc], a2m + bA2 + kc * 32);
#pragma unroll
        for (int j = 0; j < 13; j++) {
            d[j][0] = d[j][1] = d[j][2] = d[j][3] = 0.f;
#pragma unroll
            for (int kc = 0; kc < KC2; kc++) {
                uint32_t b0, b1;
                lds64u(b0, b1, b2p + (j * KC2 + kc) * 256);
                hmma(d[j], af[kc], b0, b1);
            }
        }
        // ---- epilogue 2: h2 -> A2[nb] (gemm2(t+1)); yp -> YP ring slot tc ----
        float yp = 0.f;
#pragma unroll
        for (int j = 0; j < 13; j++) {
            float t0s = odd ? d[j][0] : d[j][2];
            float t1s = odd ? d[j][1] : d[j][3];
            float rx0 = __shfl_xor_sync(0xffffffffu, t0s, 1);
            float rx1 = __shfl_xor_sync(0xffffffffu, t1s, 1);
            float gi = odd ? rx0 : d[j][0];
            float gf = odd ? rx1 : d[j][1];
            float gg = odd ? d[j][2] : rx0;
            float go = odd ? d[j][3] : rx1;
            float h = cell(gi, gf, gg, go, c2[j]);
            sts16h(hwA2 + nA2 + 104 + 4 * j, h);
            yp = fmaf(h, wl[j], yp);
        }
        sts32(ypw + (uint32_t)tc * 1024, yp);
        // no end barrier: epi2 + gemm1(t+1) overlap freely
    }

    // ---- tail: flush last chunk ----
    PBAR();
    for (int idx = ptid; idx < 256; idx += 64) {
        int rl = idx >> 4, cc = idx & 15, row = mt * 16 + rl;
        uint32_t ypb = s0 + OFF_YP + (cc * 256 + row * 4) * 4;
        float y = lds32(ypb) + lds32(ypb + 4) + lds32(ypb + 8) + lds32(ypb + 12) + bl;
        out[(rb + row) * TSEQ + (TSEQ - CHUNK) + cc] = y;
    }
#undef PBAR
}

extern "C" void kernel_launch(void* const* d_in, const int* in_sizes, int n_in,
                              void* d_out, int out_size) {
    const float* x    = (const float*)d_in[0];
    const float* Wih1 = (const float*)d_in[1];
    const float* Whh1 = (const float*)d_in[2];
    const float* bih1 = (const float*)d_in[3];
    const float* bhh1 = (const float*)d_in[4];
    const float* Wih2 = (const float*)d_in[5];
    const float* Whh2 = (const float*)d_in[6];
    const float* bih2 = (const float*)d_in[7];
    const float* bhh2 = (const float*)d_in[8];
    const float* Wlin = (const float*)d_in[9];
    const float* blin = (const float*)d_in[10];

    cudaFuncSetAttribute(lstm2_hmma_kernel,
                         cudaFuncAttributeMaxDynamicSharedMemorySize, SMEM_BYTES);
    lstm2_hmma_kernel<<<NCTA, NTH, SMEM_BYTES>>>(
        x, Wih1, Whh1, bih1, bhh1, Wih2, Whh2, bih2, bhh2, Wlin, blin,
        (float*)d_out);
}

// round 9
// speedup vs baseline: 1.0967x; 1.0369x over previous
#include <cuda_runtime.h>
#include <cuda_fp16.h>
#include <cstdint>

#define NS    51
#define ROWS  64
#define TSEQ  2048
#define BATCH 8192
#define NCTA  (BATCH / ROWS)
#define NTH   256
#define KC1   4
#define KC2   7
#define ST1   72
#define ST2   120
#define XSTR  17
#define XSBUF 4352            // one XS buffer: 64*17*4

#define A1SZ  9216
#define A2SZ  15360
#define OFF_A1   0            // single buffer
#define OFF_A2   9216         // DOUBLE buffer -> 9216 + 30720 = 39936
#define OFF_B1F  39936        // 26624 -> 66560
#define OFF_B2F  66560        // 46592 -> 113152
#define OFF_XS   113152       // 2 * 4352 -> 121856
#define OFF_YP   121856       // 16 slots * 64 rows * 4 parts * 4B = 16384 -> 138240
#define OFF_WL   138240       // 208
#define SMEM_BYTES 138496

__device__ __forceinline__ uint32_t smem_u32(const void* p) {
    uint32_t a;
    asm("{ .reg .u64 t; cvta.to.shared.u64 t, %1; cvt.u32.u64 %0, t; }" : "=r"(a) : "l"(p));
    return a;
}
__device__ __forceinline__ void sts16h(uint32_t a, float v) {
    unsigned short h = __half_as_ushort(__float2half_rn(v));
    asm volatile("st.shared.b16 [%0], %1;" :: "r"(a), "h"(h) : "memory");
}
__device__ __forceinline__ void sts32(uint32_t a, float v) {
    asm volatile("st.shared.b32 [%0], %1;" :: "r"(a), "f"(v) : "memory");
}
__device__ __forceinline__ void sts32u(uint32_t a, uint32_t v) {
    asm volatile("st.shared.b32 [%0], %1;" :: "r"(a), "r"(v) : "memory");
}
__device__ __forceinline__ float lds32(uint32_t a) {
    float v;
    asm volatile("ld.shared.b32 %0, [%1];" : "=f"(v) : "r"(a));
    return v;
}
__device__ __forceinline__ void lds64u(uint32_t& v0, uint32_t& v1, uint32_t a) {
    asm volatile("ld.shared.v2.b32 {%0,%1}, [%2];" : "=r"(v0), "=r"(v1) : "r"(a));
}
__device__ __forceinline__ void ldsm4(uint32_t* r, uint32_t a) {
    asm volatile("ldmatrix.sync.aligned.m8n8.x4.shared.b16 {%0,%1,%2,%3}, [%4];"
                 : "=r"(r[0]), "=r"(r[1]), "=r"(r[2]), "=r"(r[3]) : "r"(a));
}
__device__ __forceinline__ void hmma(float* d, const uint32_t* a, uint32_t b0, uint32_t b1) {
    asm volatile(
        "mma.sync.aligned.m16n8k16.row.col.f32.f16.f16.f32 "
        "{%0,%1,%2,%3}, {%4,%5,%6,%7}, {%8,%9}, {%0,%1,%2,%3};"
        : "+f"(d[0]), "+f"(d[1]), "+f"(d[2]), "+f"(d[3])
        : "r"(a[0]), "r"(a[1]), "r"(a[2]), "r"(a[3]), "r"(b0), "r"(b1));
}
__device__ __forceinline__ float ex2_(float x) {
    float r;
    asm("ex2.approx.ftz.f32 %0, %1;" : "=f"(r) : "f"(x));
    return r;
}
__device__ __forceinline__ float rcp_(float x) {
    float r;
    asm("rcp.approx.ftz.f32 %0, %1;" : "=f"(r) : "f"(x));
    return r;
}
// Merged LSTM cell: 5 ex2 + 2 rcp.
__device__ __forceinline__ float cell(float gi, float gf, float gg, float go, float& c) {
    const float L2E = 1.4426950408889634f;
    float a = ex2_(-L2E * gi);
    float b = ex2_(-2.f * L2E * gg);
    float u = ex2_(-L2E * gf);
    float pa = 1.f + a, pb = 1.f + b, pu = 1.f + u;
    float papb = pa * pb;
    float num = fmaf(1.f - b, pu, c * papb);
    c = num * rcp_(papb * pu);
    float o = ex2_(-L2E * go);
    float d2 = ex2_(-2.f * L2E * c);
    return (1.f - d2) * rcp_((1.f + o) * (1.f + d2));
}
// gate select from mma fragment (lanes pair-exchange via shfl)
#define GATES(dj)                                                      \
    float t0s = odd ? (dj)[0] : (dj)[2];                               \
    float t1s = odd ? (dj)[1] : (dj)[3];                               \
    float rx0 = __shfl_xor_sync(0xffffffffu, t0s, 1);                  \
    float rx1 = __shfl_xor_sync(0xffffffffu, t1s, 1);                  \
    float gi = odd ? rx0 : (dj)[0];                                    \
    float gf = odd ? rx1 : (dj)[1];                                    \
    float gg = odd ? (dj)[2] : rx0;                                    \
    float go = odd ? (dj)[3] : rx1;

__device__ float w1val(int n, int k, const float* Whh1, const float* Wih1,
                       const float* bih1, const float* bhh1) {
    int u = n >> 2, g = n & 3;
    if (u >= NS) return 0.f;
    int gu = g * NS + u;
    if (k < NS) return Whh1[gu * NS + k];
    if (k == 52) return Wih1[gu];
    if (k == 53) return bih1[gu] + bhh1[gu];
    return 0.f;
}
__device__ float w2val(int n, int k, const float* Wih2, const float* Whh2,
                       const float* bih2, const float* bhh2) {
    int u = n >> 2, g = n & 3;
    if (u >= NS) return 0.f;
    int gu = g * NS + u;
    if (k < NS) return Wih2[gu * NS + k];
    if (k >= 52 && k - 52 < NS) return Whh2[gu * NS + (k - 52)];
    if (k == 104) return bih2[gu] + bhh2[gu];
    return 0.f;
}

extern __shared__ char smraw[];

__global__ __launch_bounds__(NTH, 1)
void lstm2_hmma_kernel(const float* __restrict__ x,
                       const float* __restrict__ Wih1, const float* __restrict__ Whh1,
                       const float* __restrict__ bih1, const float* __restrict__ bhh1,
                       const float* __restrict__ Wih2, const float* __restrict__ Whh2,
                       const float* __restrict__ bih2, const float* __restrict__ bhh2,
                       const float* __restrict__ Wlin, const float* __restrict__ blin,
                       float* __restrict__ out) {
    const uint32_t s0 = smem_u32(smraw);
    const int tid = threadIdx.x;
    const int wid = tid >> 5;
    const int lane = tid & 31;
    const long long rb = (long long)blockIdx.x * ROWS;

    // ---- one-time pack ----
    for (int i = tid; i < OFF_B1F / 4; i += NTH) sts32(s0 + i * 4, 0.f);  // A1 + A2 (both bufs)
    for (int idx = tid; idx < 26 * KC1 * 64; idx += NTH) {
        int w = idx & 1, ln = (idx >> 1) & 31, kc = (idx >> 6) & 3, nt = idx >> 8;
        int n = nt * 8 + (ln >> 2);
        int k = kc * 16 + (ln & 3) * 2 + w * 8;
        __half2 hv = __floats2half2_rn(w1val(n, k, Whh1, Wih1, bih1, bhh1),
                                       w1val(n, k + 1, Whh1, Wih1, bih1, bhh1));
        sts32u(s0 + OFF_B1F + idx * 4, *reinterpret_cast<uint32_t*>(&hv));
    }
    for (int idx = tid; idx < 26 * KC2 * 64; idx += NTH) {
        int w = idx & 1, ln = (idx >> 1) & 31;
        int r = idx >> 6;
        int kc = r % KC2, nt = r / KC2;
        int n = nt * 8 + (ln >> 2);
        int k = kc * 16 + (ln & 3) * 2 + w * 8;
        __half2 hv = __floats2half2_rn(w2val(n, k, Wih2, Whh2, bih2, bhh2),
                                       w2val(n, k + 1, Wih2, Whh2, bih2, bhh2));
        sts32u(s0 + OFF_B2F + ((nt * KC2 + kc) * 64 + ln * 2 + w) * 4,
               *reinterpret_cast<uint32_t*>(&hv));
    }
    if (tid < ROWS) {   // const-1 columns (A2: both buffers)
        sts16h(s0 + OFF_A1 + (tid * ST1 + 53) * 2, 1.f);
        sts16h(s0 + OFF_A2 + (tid * ST2 + 104) * 2, 1.f);
        sts16h(s0 + OFF_A2 + A2SZ + (tid * ST2 + 104) * 2, 1.f);
    }
    for (int u = tid; u < 52; u += NTH)
        sts32(s0 + OFF_WL + u * 4, (u < NS) ? Wlin[u] : 0.f);
    // XS[0] = x(0..15); x(0) -> A1 col 52
    for (int idx = tid; idx < 1024; idx += NTH) {
        int row = idx >> 4, cc = idx & 15;
        float xv = x[(rb + row) * TSEQ + cc];
        sts32(s0 + OFF_XS + (row * XSTR + cc) * 4, xv);
        if (cc == 0) sts16h(s0 + OFF_A1 + (row * ST1 + 52) * 2, xv);
    }
    __syncthreads();

    // ---- mapping (pair warps share an SMSP) ----
    const int mt = wid & 3;
    const int nh = wid >> 2;
    const int ptid = nh * 32 + lane;
    const int barid = mt + 1;
    const bool odd = lane & 1;
    const int rowE = mt * 16 + (lane >> 2) + (odd ? 8 : 0);
    const int ubase = 26 * nh + ((lane >> 1) & 1);
    const float bl = blin[0];

    const int lrow = mt * 16 + (lane & 15);
    const uint32_t khalf = ((lane >> 4) & 1) * 16;
    const uint32_t a1m = s0 + OFF_A1 + lrow * ST1 * 2 + khalf;
    const uint32_t a2m = s0 + OFF_A2 + lrow * ST2 * 2 + khalf;
    const uint32_t b1p = s0 + OFF_B1F + (nh * 13 * KC1 * 64 + lane * 2) * 4;
    const uint32_t b2p = s0 + OFF_B2F + (nh * 13 * KC2 * 64 + lane * 2) * 4;
    const uint32_t hwA1 = s0 + OFF_A1 + rowE * ST1 * 2 + ubase * 2;
    const uint32_t hwA2 = s0 + OFF_A2 + rowE * ST2 * 2 + ubase * 2;   // +bA2 at use
    const uint32_t ypw  = s0 + OFF_YP + (rowE * 4 + nh * 2 + ((lane >> 1) & 1)) * 4;

    float wl[13];
#pragma unroll
    for (int j = 0; j < 13; j++) wl[j] = lds32(s0 + OFF_WL + (ubase + 2 * j) * 4);

    float c1[13], c2[13], d2r[13][4];
#pragma unroll
    for (int i = 0; i < 13; i++) { c1[i] = 0.f; c2[i] = 0.f; }

#define PBAR() asm volatile("bar.sync %0, 64;" :: "r"(barid) : "memory")

    for (int t = 0; t < TSEQ; t++) {
        const int tc = t & 15;
        const uint32_t bA2 = (uint32_t)(t & 1) * A2SZ;

        // ======== phase I: gemm1(t) ⊕ epi2(t-1) ========
        uint32_t af[4][4];
        float d1[13][4];
#pragma unroll
        for (int kc = 0; kc < 4; kc++) ldsm4(af[kc], a1m + kc * 32);
        if (t) {
            float yp = 0.f;
#pragma unroll
            for (int j = 0; j < 13; j++) {
                d1[j][0] = d1[j][1] = d1[j][2] = d1[j][3] = 0.f;
                uint32_t b0, b1;
#pragma unroll
                for (int kc = 0; kc < 4; kc++) {
                    lds64u(b0, b1, b1p + (j * KC1 + kc) * 256);
                    hmma(d1[j], af[kc], b0, b1);
                }
                GATES(d2r[j]);
                float h = cell(gi, gf, gg, go, c2[j]);
                sts16h(hwA2 + bA2 + 104 + 4 * j, h);   // h2(t-1) -> A2[b(t)]
                yp = fmaf(h, wl[j], yp);
            }
            sts32(ypw + (uint32_t)((t - 1) & 15) * 1024, yp);
        } else {
#pragma unroll
            for (int j = 0; j < 13; j++) {
                d1[j][0] = d1[j][1] = d1[j][2] = d1[j][3] = 0.f;
                uint32_t b0, b1;
#pragma unroll
                for (int kc = 0; kc < 4; kc++) {
                    lds64u(b0, b1, b1p + (j * KC1 + kc) * 256);
                    hmma(d1[j], af[kc], b0, b1);
                }
            }
        }

        PBAR();   // BAR_1: orders h2/A2 stores, YP stores, prior h1/x stores

        if (tc == 0) {
            if (t) {   // flush previous chunk y(t-16..t-1) straight from YP ring
                for (int idx = ptid; idx < 256; idx += 64) {
                    int rl = idx >> 4, cc = idx & 15, row = mt * 16 + rl;
                    uint32_t ypb = s0 + OFF_YP + (uint32_t)cc * 1024 + row * 16;
                    float y = lds32(ypb) + lds32(ypb + 4) + lds32(ypb + 8) + lds32(ypb + 12) + bl;
                    out[(rb + row) * TSEQ + (t - 16) + cc] = y;
                }
            }
            if (t + 16 < TSEQ) {   // stage next chunk's x
                uint32_t xb = s0 + OFF_XS + (uint32_t)(((t >> 4) + 1) & 1) * XSBUF;
                for (int idx = ptid; idx < 256; idx += 64) {
                    int rl = idx >> 4, cc = idx & 15, row = mt * 16 + rl;
                    sts32(xb + (row * XSTR + cc) * 4, x[(rb + row) * TSEQ + t + 16 + cc]);
                }
            }
        }

        // ======== phase II: epi1(t) ⊕ gemm2(t).kc4-6 ========
        uint32_t af2[3][4];
#pragma unroll
        for (int kc = 0; kc < 3; kc++) ldsm4(af2[kc], a2m + bA2 + (4 + kc) * 32);
#pragma unroll
        for (int j = 0; j < 13; j++) {
            GATES(d1[j]);
            float h = cell(gi, gf, gg, go, c1[j]);
            sts16h(hwA1 + 4 * j, h);              // h1(t) -> A1 (gemm1(t+1))
            sts16h(hwA2 + bA2 + 4 * j, h);        // h1(t) -> A2[b(t)] (kc0-3)
            d2r[j][0] = d2r[j][1] = d2r[j][2] = d2r[j][3] = 0.f;
            uint32_t b0, b1;
#pragma unroll
            for (int kc = 0; kc < 3; kc++) {
                lds64u(b0, b1, b2p + (j * KC2 + 4 + kc) * 256);
                hmma(d2r[j], af2[kc], b0, b1);
            }
        }
        if (ptid < 16 && t + 1 < TSEQ) {          // x(t+1) -> A1 col 52
            int row = mt * 16 + ptid;
            uint32_t xb = s0 + OFF_XS + (uint32_t)(((t + 1) >> 4) & 1) * XSBUF;
            sts16h(s0 + OFF_A1 + (row * ST1 + 52) * 2,
                   lds32(xb + (row * XSTR + ((t + 1) & 15)) * 4));
        }

        PBAR();   // BAR_2: orders h1/A2, h1/A1, x stores

        // ======== phase III: gemm2(t).kc0-3 (d2 carried to next phase I) ========
#pragma unroll
        for (int kc = 0; kc < 4; kc++) ldsm4(af[kc], a2m + bA2 + kc * 32);
#pragma unroll
        for (int j = 0; j < 13; j++) {
            uint32_t b0, b1;
#pragma unroll
            for (int kc = 0; kc < 4; kc++) {
                lds64u(b0, b1, b2p + (j * KC2 + kc) * 256);
                hmma(d2r[j], af[kc], b0, b1);
            }
        }
    }

    // ---- epilogue: epi2(T-1) + final chunk flush ----
    {
        float yp = 0.f;
#pragma unroll
        for (int j = 0; j < 13; j++) {
            GATES(d2r[j]);
            float h = cell(gi, gf, gg, go, c2[j]);
            yp = fmaf(h, wl[j], yp);
        }
        sts32(ypw + 15u * 1024, yp);
    }
    PBAR();
    for (int idx = ptid; idx < 256; idx += 64) {
        int rl = idx >> 4, cc = idx & 15, row = mt * 16 + rl;
        uint32_t ypb = s0 + OFF_YP + (uint32_t)cc * 1024 + row * 16;
        float y = lds32(ypb) + lds32(ypb + 4) + lds32(ypb + 8) + lds32(ypb + 12) + bl;
        out[(rb + row) * TSEQ + (TSEQ - 16) + cc] = y;
    }
#undef PBAR
}

extern "C" void kernel_launch(void* const* d_in, const int* in_sizes, int n_in,
                              void* d_out, int out_size) {
    const float* x    = (const float*)d_in[0];
    const float* Wih1 = (const float*)d_in[1];
    const float* Whh1 = (const float*)d_in[2];
    const float* bih1 = (const float*)d_in[3];
    const float* bhh1 = (const float*)d_in[4];
    const float* Wih2 = (const float*)d_in[5];
    const float* Whh2 = (const float*)d_in[6];
    const float* bih2 = (const float*)d_in[7];
    const float* bhh2 = (const float*)d_in[8];
    const float* Wlin = (const float*)d_in[9];
    const float* blin = (const float*)d_in[10];

    cudaFuncSetAttribute(lstm2_hmma_kernel,
                         cudaFuncAttributeMaxDynamicSharedMemorySize, SMEM_BYTES);
    lstm2_hmma_kernel<<<NCTA, NTH, SMEM_BYTES>>>(
        x, Wih1, Whh1, bih1, bhh1, Wih2, Whh2, bih2, bhh2, Wlin, blin,
        (float*)d_out);
}